// round 3
// baseline (speedup 1.0000x reference)
#include <cuda_runtime.h>

#define BB 16
#define NN 256
#define HIDD 512
#define HH 8
#define DKK 64
#define FEATF 8
#define MLPH 64
#define BN (BB*NN)   // 4096

__device__ __align__(256) float g_qh[BN*HIDD];
__device__ __align__(256) float g_kh[BN*HIDD];
__device__ __align__(256) float g_vh[BN*HIDD];
__device__ __align__(256) float g_x [BN*HIDD];
__device__ __align__(256) float g_scores[BB*HH*NN*NN];
__device__ __align__(256) float g_hiS[BN*MLPH];
__device__ __align__(256) float g_hjS[BN*MLPH];
__device__ __align__(256) float g_hiO[BN*MLPH];
__device__ __align__(256) float g_hjO[BN*MLPH];

// ---------------------------------------------------------------------------
// C[M,512] = scale * (A[M,512] @ W[512,512] + bias)
// 64x64 block tile, 256 threads, 4x4 per thread, k-chunk 16.
// ---------------------------------------------------------------------------
__global__ __launch_bounds__(256) void gemm512_kernel(
    const float* __restrict__ A, const float* __restrict__ W,
    const float* __restrict__ bias, float* __restrict__ C, float scale)
{
    __shared__ float As[16*68];  // [k][i]
    __shared__ float Ws[16*68];  // [k][j]
    int t  = threadIdx.x;
    int tx = t & 15, ty = t >> 4;
    int row0 = blockIdx.y * 64;
    int col0 = blockIdx.x * 64;
    float acc[4][4] = {};

    for (int kc = 0; kc < 512; kc += 16) {
        {   // A tile: 64 rows x 16 k, store transposed [k][i]
            int r  = t >> 2;
            int c4 = (t & 3) * 4;
            float4 a4 = *(const float4*)&A[(row0 + r)*512 + kc + c4];
            As[(c4+0)*68 + r] = a4.x;
            As[(c4+1)*68 + r] = a4.y;
            As[(c4+2)*68 + r] = a4.z;
            As[(c4+3)*68 + r] = a4.w;
        }
        {   // W tile: 16 k x 64 j, natural
            int r  = t >> 4;
            int c4 = (t & 15) * 4;
            *(float4*)&Ws[r*68 + c4] = *(const float4*)&W[(kc + r)*512 + col0 + c4];
        }
        __syncthreads();
        #pragma unroll
        for (int kk = 0; kk < 16; kk++) {
            float4 a4 = *(const float4*)&As[kk*68 + ty*4];
            float4 b4 = *(const float4*)&Ws[kk*68 + tx*4];
            float av[4] = {a4.x, a4.y, a4.z, a4.w};
            float bv[4] = {b4.x, b4.y, b4.z, b4.w};
            #pragma unroll
            for (int i = 0; i < 4; i++)
                #pragma unroll
                for (int j = 0; j < 4; j++)
                    acc[i][j] += av[i] * bv[j];
        }
        __syncthreads();
    }
    #pragma unroll
    for (int i = 0; i < 4; i++) {
        int row = row0 + ty*4 + i;
        float4 o;
        o.x = scale * (acc[i][0] + bias[col0 + tx*4 + 0]);
        o.y = scale * (acc[i][1] + bias[col0 + tx*4 + 1]);
        o.z = scale * (acc[i][2] + bias[col0 + tx*4 + 2]);
        o.w = scale * (acc[i][3] + bias[col0 + tx*4 + 3]);
        *(float4*)&C[row*512 + col0 + tx*4] = o;
    }
}

// ---------------------------------------------------------------------------
// Per-node MLP halves: hi = feat@W1[0:8] + b1 (b1 folded), hj = feat@W1[8:16]
// for both storage and operator features.
// ---------------------------------------------------------------------------
__global__ void hfeat_kernel(
    const float* __restrict__ fs, const float* __restrict__ fo,
    const float* __restrict__ fsW1, const float* __restrict__ fsb1,
    const float* __restrict__ foW1, const float* __restrict__ fob1)
{
    int idx = blockIdx.x * blockDim.x + threadIdx.x;
    if (idx >= BN*MLPH) return;
    int bn = idx >> 6, m = idx & 63;
    float s_i = fsb1[m], s_j = 0.f, o_i = fob1[m], o_j = 0.f;
    #pragma unroll
    for (int f = 0; f < 8; f++) {
        float vs = fs[bn*8 + f], vo = fo[bn*8 + f];
        s_i += vs * fsW1[f*64 + m];
        s_j += vs * fsW1[(8+f)*64 + m];
        o_i += vo * foW1[f*64 + m];
        o_j += vo * foW1[(8+f)*64 + m];
    }
    g_hiS[idx] = s_i; g_hjS[idx] = s_j; g_hiO[idx] = o_i; g_hjO[idx] = o_j;
}

// ---------------------------------------------------------------------------
// scores[b,h,i,j] = qh . kh + tree_bias   (per (b,h): 256x256x64 GEMM)
// ---------------------------------------------------------------------------
__global__ __launch_bounds__(256) void scores_kernel(const float* __restrict__ tbias)
{
    __shared__ float Qs[64*68];  // [d][i]
    __shared__ float Ks[64*68];  // [d][j]
    int t  = threadIdx.x;
    int tx = t & 15, ty = t >> 4;
    int j0 = blockIdx.x * 64, i0 = blockIdx.y * 64;
    int bh = blockIdx.z; int b = bh >> 3, h = bh & 7;

    #pragma unroll
    for (int u = 0; u < 4; u++) {
        int idx = t + u*256;
        int r = idx >> 4;
        int c4 = (idx & 15) * 4;
        float4 q4 = *(const float4*)&g_qh[(b*NN + i0 + r)*HIDD + h*64 + c4];
        Qs[(c4+0)*68 + r] = q4.x; Qs[(c4+1)*68 + r] = q4.y;
        Qs[(c4+2)*68 + r] = q4.z; Qs[(c4+3)*68 + r] = q4.w;
        float4 k4 = *(const float4*)&g_kh[(b*NN + j0 + r)*HIDD + h*64 + c4];
        Ks[(c4+0)*68 + r] = k4.x; Ks[(c4+1)*68 + r] = k4.y;
        Ks[(c4+2)*68 + r] = k4.z; Ks[(c4+3)*68 + r] = k4.w;
    }
    __syncthreads();

    float acc[4][4] = {};
    #pragma unroll 8
    for (int k = 0; k < 64; k++) {
        float4 a4 = *(const float4*)&Qs[k*68 + ty*4];
        float4 b4 = *(const float4*)&Ks[k*68 + tx*4];
        float av[4] = {a4.x, a4.y, a4.z, a4.w};
        float bv[4] = {b4.x, b4.y, b4.z, b4.w};
        #pragma unroll
        for (int i = 0; i < 4; i++)
            #pragma unroll
            for (int j = 0; j < 4; j++)
                acc[i][j] += av[i] * bv[j];
    }

    #pragma unroll
    for (int i = 0; i < 4; i++) {
        int gi = i0 + ty*4 + i;
        int base = ((b*HH + h)*NN + gi)*NN + j0 + tx*4;
        float4 bb = *(const float4*)&tbias[base];
        float4 o;
        o.x = acc[i][0] + bb.x; o.y = acc[i][1] + bb.y;
        o.z = acc[i][2] + bb.z; o.w = acc[i][3] + bb.w;
        *(float4*)&g_scores[base] = o;
    }
}

// ---------------------------------------------------------------------------
// Pair-bias MLPs, fused add into scores:
// scores[b,h,i,j] += LAM * ( relu(hiS_i + hjS_j + |di-dj|@WcS) @ W2S + b2S
//                          + relu(hiO_i + hjO_j + |..|@WcO)    @ W2O + b2O )[h]
// Block: 16 i x 64 j (16 tj threads x 4 j each). hj staged transposed [m][j].
// ---------------------------------------------------------------------------
__global__ __launch_bounds__(256) void pair_kernel(
    const float* __restrict__ fs, const float* __restrict__ fo,
    const float* __restrict__ fsW1, const float* __restrict__ fsW2, const float* __restrict__ fsb2,
    const float* __restrict__ foW1, const float* __restrict__ foW2, const float* __restrict__ fob2)
{
    extern __shared__ float sm[];
    float* hiS = sm;                 // 16*68
    float* hiO = hiS + 16*68;        // 16*68
    float* hjS = hiO + 16*68;        // 64*68 [m][j]
    float* hjO = hjS + 64*68;        // 64*68
    float* WcS = hjO + 64*68;        // [f][m] 8*64
    float* WcO = WcS + 512;
    float* W2S = WcO + 512;          // [m][h] 64*8
    float* W2O = W2S + 512;

    int t  = threadIdx.x;
    int b  = blockIdx.z;
    int i0 = blockIdx.y * 16;
    int j0 = blockIdx.x * 64;

    {   // hi tiles: 16 x 64
        int r = t >> 4, c4 = (t & 15) * 4;
        *(float4*)&hiS[r*68 + c4] = *(const float4*)&g_hiS[(b*NN + i0 + r)*64 + c4];
        *(float4*)&hiO[r*68 + c4] = *(const float4*)&g_hiO[(b*NN + i0 + r)*64 + c4];
    }
    #pragma unroll
    for (int u = 0; u < 4; u++) {    // hj tiles transposed: 64 j x 64 m
        int idx = t + u*256;
        int jr = idx >> 4, c4 = (idx & 15) * 4;
        float4 v = *(const float4*)&g_hjS[(b*NN + j0 + jr)*64 + c4];
        hjS[(c4+0)*68 + jr] = v.x; hjS[(c4+1)*68 + jr] = v.y;
        hjS[(c4+2)*68 + jr] = v.z; hjS[(c4+3)*68 + jr] = v.w;
        float4 w = *(const float4*)&g_hjO[(b*NN + j0 + jr)*64 + c4];
        hjO[(c4+0)*68 + jr] = w.x; hjO[(c4+1)*68 + jr] = w.y;
        hjO[(c4+2)*68 + jr] = w.z; hjO[(c4+3)*68 + jr] = w.w;
    }
    if (t < 128) {                   // weights
        *(float4*)&WcS[t*4] = *(const float4*)&fsW1[16*64 + t*4];
        *(float4*)&WcO[t*4] = *(const float4*)&foW1[16*64 + t*4];
        *(float4*)&W2S[t*4] = *(const float4*)&fsW2[t*4];
        *(float4*)&W2O[t*4] = *(const float4*)&foW2[t*4];
    }
    __syncthreads();

    int ti = t >> 4;                 // 0..15 -> i
    int tj = t & 15;                 // 0..15 -> 4 j's
    int i  = i0 + ti;

    float dS[4][8], dO[4][8];
    {
        float fiS[8], fiO[8];
        #pragma unroll
        for (int f = 0; f < 8; f++) {
            fiS[f] = fs[(b*NN + i)*8 + f];
            fiO[f] = fo[(b*NN + i)*8 + f];
        }
        #pragma unroll
        for (int jj = 0; jj < 4; jj++) {
            int j = j0 + tj*4 + jj;
            #pragma unroll
            for (int f = 0; f < 8; f++) {
                dS[jj][f] = fabsf(fiS[f] - fs[(b*NN + j)*8 + f]);
                dO[jj][f] = fabsf(fiO[f] - fo[(b*NN + j)*8 + f]);
            }
        }
    }

    float p[4][8];
    #pragma unroll
    for (int jj = 0; jj < 4; jj++)
        #pragma unroll
        for (int hh = 0; hh < 8; hh++)
            p[jj][hh] = fsb2[hh] + fob2[hh];

    for (int m = 0; m < 64; m++) {
        float aS = hiS[ti*68 + m];
        float aO = hiO[ti*68 + m];
        float4 hS4 = *(const float4*)&hjS[m*68 + tj*4];
        float4 hO4 = *(const float4*)&hjO[m*68 + tj*4];
        float uS[4] = {aS + hS4.x, aS + hS4.y, aS + hS4.z, aS + hS4.w};
        float uO[4] = {aO + hO4.x, aO + hO4.y, aO + hO4.z, aO + hO4.w};
        #pragma unroll
        for (int f = 0; f < 8; f++) {
            float wS = WcS[f*64 + m], wO = WcO[f*64 + m];
            #pragma unroll
            for (int jj = 0; jj < 4; jj++) {
                uS[jj] += dS[jj][f] * wS;
                uO[jj] += dO[jj][f] * wO;
            }
        }
        #pragma unroll
        for (int jj = 0; jj < 4; jj++) {
            uS[jj] = fmaxf(uS[jj], 0.f);
            uO[jj] = fmaxf(uO[jj], 0.f);
        }
        #pragma unroll
        for (int hh = 0; hh < 8; hh++) {
            float w2s = W2S[m*8 + hh], w2o = W2O[m*8 + hh];
            #pragma unroll
            for (int jj = 0; jj < 4; jj++)
                p[jj][hh] += uS[jj]*w2s + uO[jj]*w2o;
        }
    }

    #pragma unroll
    for (int hh = 0; hh < 8; hh++) {
        float* sp = &g_scores[((b*HH + hh)*NN + i)*NN + j0 + tj*4];
        float4 s = *(float4*)sp;
        s.x += 0.1f * p[0][hh];
        s.y += 0.1f * p[1][hh];
        s.z += 0.1f * p[2][hh];
        s.w += 0.1f * p[3][hh];
        *(float4*)sp = s;
    }
}

// ---------------------------------------------------------------------------
// Row softmax over j (one warp per row of 256)
// ---------------------------------------------------------------------------
__global__ void softmax_kernel()
{
    int warp = (blockIdx.x * blockDim.x + threadIdx.x) >> 5;
    int lane = threadIdx.x & 31;
    if (warp >= BB*HH*NN) return;
    float* row = &g_scores[(size_t)warp * NN];
    float4 v0 = *(float4*)&row[lane*8];
    float4 v1 = *(float4*)&row[lane*8 + 4];
    float mx = fmaxf(fmaxf(fmaxf(v0.x, v0.y), fmaxf(v0.z, v0.w)),
                     fmaxf(fmaxf(v1.x, v1.y), fmaxf(v1.z, v1.w)));
    #pragma unroll
    for (int o = 16; o > 0; o >>= 1)
        mx = fmaxf(mx, __shfl_xor_sync(0xffffffffu, mx, o));
    v0.x = __expf(v0.x - mx); v0.y = __expf(v0.y - mx);
    v0.z = __expf(v0.z - mx); v0.w = __expf(v0.w - mx);
    v1.x = __expf(v1.x - mx); v1.y = __expf(v1.y - mx);
    v1.z = __expf(v1.z - mx); v1.w = __expf(v1.w - mx);
    float sm = v0.x + v0.y + v0.z + v0.w + v1.x + v1.y + v1.z + v1.w;
    #pragma unroll
    for (int o = 16; o > 0; o >>= 1)
        sm += __shfl_xor_sync(0xffffffffu, sm, o);
    float inv = 1.f / sm;
    v0.x *= inv; v0.y *= inv; v0.z *= inv; v0.w *= inv;
    v1.x *= inv; v1.y *= inv; v1.z *= inv; v1.w *= inv;
    *(float4*)&row[lane*8]     = v0;
    *(float4*)&row[lane*8 + 4] = v1;
}

// ---------------------------------------------------------------------------
// x[b,i,h*64+d] = sum_j attn[b,h,i,j] * vh[b,j,h*64+d]
// ---------------------------------------------------------------------------
__global__ __launch_bounds__(256) void attnv_kernel()
{
    __shared__ float As[64*68];  // [j][i]
    __shared__ float Vs[64*68];  // [j][d]
    int t  = threadIdx.x;
    int tx = t & 15, ty = t >> 4;
    int i0 = blockIdx.x * 64;
    int bh = blockIdx.y; int b = bh >> 3, h = bh & 7;
    float acc[4][4] = {};

    for (int jc = 0; jc < NN; jc += 64) {
        #pragma unroll
        for (int u = 0; u < 4; u++) {
            int idx = t + u*256;
            int r = idx >> 4, c4 = (idx & 15) * 4;
            float4 a4 = *(const float4*)&g_scores[((b*HH + h)*NN + i0 + r)*NN + jc + c4];
            As[(c4+0)*68 + r] = a4.x; As[(c4+1)*68 + r] = a4.y;
            As[(c4+2)*68 + r] = a4.z; As[(c4+3)*68 + r] = a4.w;
            float4 v4 = *(const float4*)&g_vh[(b*NN + jc + r)*HIDD + h*64 + c4];
            *(float4*)&Vs[r*68 + c4] = v4;
        }
        __syncthreads();
        #pragma unroll 8
        for (int j = 0; j < 64; j++) {
            float4 a4 = *(const float4*)&As[j*68 + ty*4];
            float4 b4 = *(const float4*)&Vs[j*68 + tx*4];
            float av[4] = {a4.x, a4.y, a4.z, a4.w};
            float bv[4] = {b4.x, b4.y, b4.z, b4.w};
            #pragma unroll
            for (int i = 0; i < 4; i++)
                #pragma unroll
                for (int j2 = 0; j2 < 4; j2++)
                    acc[i][j2] += av[i] * bv[j2];
        }
        __syncthreads();
    }
    #pragma unroll
    for (int i = 0; i < 4; i++) {
        float4 o = {acc[i][0], acc[i][1], acc[i][2], acc[i][3]};
        *(float4*)&g_x[(b*NN + i0 + ty*4 + i)*HIDD + h*64 + tx*4] = o;
    }
}

// ---------------------------------------------------------------------------
extern "C" void kernel_launch(void* const* d_in, const int* in_sizes, int n_in,
                              void* d_out, int out_size)
{
    const float* q     = (const float*)d_in[0];
    const float* k     = (const float*)d_in[1];
    const float* v     = (const float*)d_in[2];
    const float* tbias = (const float*)d_in[3];
    const float* fs    = (const float*)d_in[4];
    const float* fo    = (const float*)d_in[5];
    const float* Wq    = (const float*)d_in[6];
    const float* bq    = (const float*)d_in[7];
    const float* Wk    = (const float*)d_in[8];
    const float* bk    = (const float*)d_in[9];
    const float* Wv    = (const float*)d_in[10];
    const float* bv    = (const float*)d_in[11];
    const float* Wo    = (const float*)d_in[12];
    const float* bo    = (const float*)d_in[13];
    const float* fsW1  = (const float*)d_in[14];
    const float* fsb1  = (const float*)d_in[15];
    const float* fsW2  = (const float*)d_in[16];
    const float* fsb2  = (const float*)d_in[17];
    const float* foW1  = (const float*)d_in[18];
    const float* fob1  = (const float*)d_in[19];
    const float* foW2  = (const float*)d_in[20];
    const float* fob2  = (const float*)d_in[21];
    float* out = (float*)d_out;

    float* qh; cudaGetSymbolAddress((void**)&qh, g_qh);
    float* kh; cudaGetSymbolAddress((void**)&kh, g_kh);
    float* vh; cudaGetSymbolAddress((void**)&vh, g_vh);
    float* x;  cudaGetSymbolAddress((void**)&x,  g_x);

    cudaFuncSetAttribute(pair_kernel,
                         cudaFuncAttributeMaxDynamicSharedMemorySize, 51712);

    dim3 gg(8, 64);
    gemm512_kernel<<<gg, 256>>>(q, Wq, bq, qh, 0.125f);
    gemm512_kernel<<<gg, 256>>>(k, Wk, bk, kh, 1.0f);
    gemm512_kernel<<<gg, 256>>>(v, Wv, bv, vh, 1.0f);

    hfeat_kernel<<<(BN*MLPH + 255)/256, 256>>>(fs, fo, fsW1, fsb1, foW1, fob1);

    scores_kernel<<<dim3(4, 4, BB*HH), 256>>>(tbias);

    pair_kernel<<<dim3(4, 16, BB), 256, 51712>>>(fs, fo, fsW1, fsW2, fsb2,
                                                 foW1, foW2, fob2);

    softmax_kernel<<<(BB*HH*NN*32 + 255)/256, 256>>>();

    attnv_kernel<<<dim3(4, BB*HH), 256>>>();

    gemm512_kernel<<<gg, 256>>>(x, Wo, bo, out, 1.0f);
}

// round 6
// speedup vs baseline: 1.0023x; 1.0023x over previous
#include <cuda_runtime.h>

#define BB 16
#define NN 256
#define HIDD 512
#define HH 8
#define DKK 64
#define FEATF 8
#define MLPH 64
#define BN (BB*NN)   // 4096

__device__ __align__(256) float g_qh[BN*HIDD];
__device__ __align__(256) float g_kh[BN*HIDD];
__device__ __align__(256) float g_vh[BN*HIDD];
__device__ __align__(256) float g_x [BN*HIDD];
__device__ __align__(256) float g_scores[BB*HH*NN*NN];
__device__ __align__(256) float g_hiS[BN*MLPH];
__device__ __align__(256) float g_hjS[BN*MLPH];
__device__ __align__(256) float g_hiO[BN*MLPH];
__device__ __align__(256) float g_hjO[BN*MLPH];

// ---------------------------------------------------------------------------
// C[M,512] = scale * (A[M,512] @ W[512,512] + bias)
// 64x64 block tile, 256 threads, 4x4 per thread, k-chunk 16.
// ---------------------------------------------------------------------------
__global__ __launch_bounds__(256) void gemm512_kernel(
    const float* __restrict__ A, const float* __restrict__ W,
    const float* __restrict__ bias, float* __restrict__ C, float scale)
{
    __shared__ float As[16*68];  // [k][i]
    __shared__ float Ws[16*68];  // [k][j]
    int t  = threadIdx.x;
    int tx = t & 15, ty = t >> 4;
    int row0 = blockIdx.y * 64;
    int col0 = blockIdx.x * 64;
    float acc[4][4] = {};

    for (int kc = 0; kc < 512; kc += 16) {
        {   // A tile: 64 rows x 16 k, store transposed [k][i]
            int r  = t >> 2;
            int c4 = (t & 3) * 4;
            float4 a4 = *(const float4*)&A[(row0 + r)*512 + kc + c4];
            As[(c4+0)*68 + r] = a4.x;
            As[(c4+1)*68 + r] = a4.y;
            As[(c4+2)*68 + r] = a4.z;
            As[(c4+3)*68 + r] = a4.w;
        }
        {   // W tile: 16 k x 64 j, natural
            int r  = t >> 4;
            int c4 = (t & 15) * 4;
            *(float4*)&Ws[r*68 + c4] = *(const float4*)&W[(kc + r)*512 + col0 + c4];
        }
        __syncthreads();
        #pragma unroll
        for (int kk = 0; kk < 16; kk++) {
            float4 a4 = *(const float4*)&As[kk*68 + ty*4];
            float4 b4 = *(const float4*)&Ws[kk*68 + tx*4];
            float av[4] = {a4.x, a4.y, a4.z, a4.w};
            float bv[4] = {b4.x, b4.y, b4.z, b4.w};
            #pragma unroll
            for (int i = 0; i < 4; i++)
                #pragma unroll
                for (int j = 0; j < 4; j++)
                    acc[i][j] += av[i] * bv[j];
        }
        __syncthreads();
    }
    #pragma unroll
    for (int i = 0; i < 4; i++) {
        int row = row0 + ty*4 + i;
        float4 o;
        o.x = scale * (acc[i][0] + bias[col0 + tx*4 + 0]);
        o.y = scale * (acc[i][1] + bias[col0 + tx*4 + 1]);
        o.z = scale * (acc[i][2] + bias[col0 + tx*4 + 2]);
        o.w = scale * (acc[i][3] + bias[col0 + tx*4 + 3]);
        *(float4*)&C[row*512 + col0 + tx*4] = o;
    }
}

// ---------------------------------------------------------------------------
// Per-node MLP halves: hi = feat@W1[0:8] + b1 (b1 folded), hj = feat@W1[8:16]
// for both storage and operator features.
// ---------------------------------------------------------------------------
__global__ void hfeat_kernel(
    const float* __restrict__ fs, const float* __restrict__ fo,
    const float* __restrict__ fsW1, const float* __restrict__ fsb1,
    const float* __restrict__ foW1, const float* __restrict__ fob1)
{
    int idx = blockIdx.x * blockDim.x + threadIdx.x;
    if (idx >= BN*MLPH) return;
    int bn = idx >> 6, m = idx & 63;
    float s_i = fsb1[m], s_j = 0.f, o_i = fob1[m], o_j = 0.f;
    #pragma unroll
    for (int f = 0; f < 8; f++) {
        float vs = fs[bn*8 + f], vo = fo[bn*8 + f];
        s_i += vs * fsW1[f*64 + m];
        s_j += vs * fsW1[(8+f)*64 + m];
        o_i += vo * foW1[f*64 + m];
        o_j += vo * foW1[(8+f)*64 + m];
    }
    g_hiS[idx] = s_i; g_hjS[idx] = s_j; g_hiO[idx] = o_i; g_hjO[idx] = o_j;
}

// ---------------------------------------------------------------------------
// scores[b,h,i,j] = qh . kh + tree_bias   (per (b,h): 256x256x64 GEMM)
// ---------------------------------------------------------------------------
__global__ __launch_bounds__(256) void scores_kernel(const float* __restrict__ tbias)
{
    __shared__ float Qs[64*68];  // [d][i]
    __shared__ float Ks[64*68];  // [d][j]
    int t  = threadIdx.x;
    int tx = t & 15, ty = t >> 4;
    int j0 = blockIdx.x * 64, i0 = blockIdx.y * 64;
    int bh = blockIdx.z; int b = bh >> 3, h = bh & 7;

    #pragma unroll
    for (int u = 0; u < 4; u++) {
        int idx = t + u*256;
        int r = idx >> 4;
        int c4 = (idx & 15) * 4;
        float4 q4 = *(const float4*)&g_qh[(b*NN + i0 + r)*HIDD + h*64 + c4];
        Qs[(c4+0)*68 + r] = q4.x; Qs[(c4+1)*68 + r] = q4.y;
        Qs[(c4+2)*68 + r] = q4.z; Qs[(c4+3)*68 + r] = q4.w;
        float4 k4 = *(const float4*)&g_kh[(b*NN + j0 + r)*HIDD + h*64 + c4];
        Ks[(c4+0)*68 + r] = k4.x; Ks[(c4+1)*68 + r] = k4.y;
        Ks[(c4+2)*68 + r] = k4.z; Ks[(c4+3)*68 + r] = k4.w;
    }
    __syncthreads();

    float acc[4][4] = {};
    #pragma unroll 8
    for (int k = 0; k < 64; k++) {
        float4 a4 = *(const float4*)&Qs[k*68 + ty*4];
        float4 b4 = *(const float4*)&Ks[k*68 + tx*4];
        float av[4] = {a4.x, a4.y, a4.z, a4.w};
        float bv[4] = {b4.x, b4.y, b4.z, b4.w};
        #pragma unroll
        for (int i = 0; i < 4; i++)
            #pragma unroll
            for (int j = 0; j < 4; j++)
                acc[i][j] += av[i] * bv[j];
    }

    #pragma unroll
    for (int i = 0; i < 4; i++) {
        int gi = i0 + ty*4 + i;
        int base = ((b*HH + h)*NN + gi)*NN + j0 + tx*4;
        float4 bb = *(const float4*)&tbias[base];
        float4 o;
        o.x = acc[i][0] + bb.x; o.y = acc[i][1] + bb.y;
        o.z = acc[i][2] + bb.z; o.w = acc[i][3] + bb.w;
        *(float4*)&g_scores[base] = o;
    }
}

// ---------------------------------------------------------------------------
// Pair-bias MLPs, fused add into scores:
// scores[b,h,i,j] += LAM * ( relu(hiS_i + hjS_j + |di-dj|@WcS) @ W2S + b2S
//                          + relu(hiO_i + hjO_j + |..|@WcO)    @ W2O + b2O )[h]
// Block: 16 i x 64 j (16 tj threads x 4 j each). hj staged transposed [m][j].
// ---------------------------------------------------------------------------
__global__ __launch_bounds__(256) void pair_kernel(
    const float* __restrict__ fs, const float* __restrict__ fo,
    const float* __restrict__ fsW1, const float* __restrict__ fsW2, const float* __restrict__ fsb2,
    const float* __restrict__ foW1, const float* __restrict__ foW2, const float* __restrict__ fob2)
{
    extern __shared__ float sm[];
    float* hiS = sm;                 // 16*68
    float* hiO = hiS + 16*68;        // 16*68
    float* hjS = hiO + 16*68;        // 64*68 [m][j]
    float* hjO = hjS + 64*68;        // 64*68
    float* WcS = hjO + 64*68;        // [f][m] 8*64
    float* WcO = WcS + 512;
    float* W2S = WcO + 512;          // [m][h] 64*8
    float* W2O = W2S + 512;

    int t  = threadIdx.x;
    int b  = blockIdx.z;
    int i0 = blockIdx.y * 16;
    int j0 = blockIdx.x * 64;

    {   // hi tiles: 16 x 64
        int r = t >> 4, c4 = (t & 15) * 4;
        *(float4*)&hiS[r*68 + c4] = *(const float4*)&g_hiS[(b*NN + i0 + r)*64 + c4];
        *(float4*)&hiO[r*68 + c4] = *(const float4*)&g_hiO[(b*NN + i0 + r)*64 + c4];
    }
    #pragma unroll
    for (int u = 0; u < 4; u++) {    // hj tiles transposed: 64 j x 64 m
        int idx = t + u*256;
        int jr = idx >> 4, c4 = (idx & 15) * 4;
        float4 v = *(const float4*)&g_hjS[(b*NN + j0 + jr)*64 + c4];
        hjS[(c4+0)*68 + jr] = v.x; hjS[(c4+1)*68 + jr] = v.y;
        hjS[(c4+2)*68 + jr] = v.z; hjS[(c4+3)*68 + jr] = v.w;
        float4 w = *(const float4*)&g_hjO[(b*NN + j0 + jr)*64 + c4];
        hjO[(c4+0)*68 + jr] = w.x; hjO[(c4+1)*68 + jr] = w.y;
        hjO[(c4+2)*68 + jr] = w.z; hjO[(c4+3)*68 + jr] = w.w;
    }
    if (t < 128) {                   // weights
        *(float4*)&WcS[t*4] = *(const float4*)&fsW1[16*64 + t*4];
        *(float4*)&WcO[t*4] = *(const float4*)&foW1[16*64 + t*4];
        *(float4*)&W2S[t*4] = *(const float4*)&fsW2[t*4];
        *(float4*)&W2O[t*4] = *(const float4*)&foW2[t*4];
    }
    __syncthreads();

    int ti = t >> 4;                 // 0..15 -> i
    int tj = t & 15;                 // 0..15 -> 4 j's
    int i  = i0 + ti;

    float dS[4][8], dO[4][8];
    {
        float fiS[8], fiO[8];
        #pragma unroll
        for (int f = 0; f < 8; f++) {
            fiS[f] = fs[(b*NN + i)*8 + f];
            fiO[f] = fo[(b*NN + i)*8 + f];
        }
        #pragma unroll
        for (int jj = 0; jj < 4; jj++) {
            int j = j0 + tj*4 + jj;
            #pragma unroll
            for (int f = 0; f < 8; f++) {
                dS[jj][f] = fabsf(fiS[f] - fs[(b*NN + j)*8 + f]);
                dO[jj][f] = fabsf(fiO[f] - fo[(b*NN + j)*8 + f]);
            }
        }
    }

    float p[4][8];
    #pragma unroll
    for (int jj = 0; jj < 4; jj++)
        #pragma unroll
        for (int hh = 0; hh < 8; hh++)
            p[jj][hh] = fsb2[hh] + fob2[hh];

    for (int m = 0; m < 64; m++) {
        float aS = hiS[ti*68 + m];
        float aO = hiO[ti*68 + m];
        float4 hS4 = *(const float4*)&hjS[m*68 + tj*4];
        float4 hO4 = *(const float4*)&hjO[m*68 + tj*4];
        float uS[4] = {aS + hS4.x, aS + hS4.y, aS + hS4.z, aS + hS4.w};
        float uO[4] = {aO + hO4.x, aO + hO4.y, aO + hO4.z, aO + hO4.w};
        #pragma unroll
        for (int f = 0; f < 8; f++) {
            float wS = WcS[f*64 + m], wO = WcO[f*64 + m];
            #pragma unroll
            for (int jj = 0; jj < 4; jj++) {
                uS[jj] += dS[jj][f] * wS;
                uO[jj] += dO[jj][f] * wO;
            }
        }
        #pragma unroll
        for (int jj = 0; jj < 4; jj++) {
            uS[jj] = fmaxf(uS[jj], 0.f);
            uO[jj] = fmaxf(uO[jj], 0.f);
        }
        #pragma unroll
        for (int hh = 0; hh < 8; hh++) {
            float w2s = W2S[m*8 + hh], w2o = W2O[m*8 + hh];
            #pragma unroll
            for (int jj = 0; jj < 4; jj++)
                p[jj][hh] += uS[jj]*w2s + uO[jj]*w2o;
        }
    }

    #pragma unroll
    for (int hh = 0; hh < 8; hh++) {
        float* sp = &g_scores[((b*HH + hh)*NN + i)*NN + j0 + tj*4];
        float4 s = *(float4*)sp;
        s.x += 0.1f * p[0][hh];
        s.y += 0.1f * p[1][hh];
        s.z += 0.1f * p[2][hh];
        s.w += 0.1f * p[3][hh];
        *(float4*)sp = s;
    }
}

// ---------------------------------------------------------------------------
// Row softmax over j (one warp per row of 256)
// ---------------------------------------------------------------------------
__global__ void softmax_kernel()
{
    int warp = (blockIdx.x * blockDim.x + threadIdx.x) >> 5;
    int lane = threadIdx.x & 31;
    if (warp >= BB*HH*NN) return;
    float* row = &g_scores[(size_t)warp * NN];
    float4 v0 = *(float4*)&row[lane*8];
    float4 v1 = *(float4*)&row[lane*8 + 4];
    float mx = fmaxf(fmaxf(fmaxf(v0.x, v0.y), fmaxf(v0.z, v0.w)),
                     fmaxf(fmaxf(v1.x, v1.y), fmaxf(v1.z, v1.w)));
    #pragma unroll
    for (int o = 16; o > 0; o >>= 1)
        mx = fmaxf(mx, __shfl_xor_sync(0xffffffffu, mx, o));
    v0.x = __expf(v0.x - mx); v0.y = __expf(v0.y - mx);
    v0.z = __expf(v0.z - mx); v0.w = __expf(v0.w - mx);
    v1.x = __expf(v1.x - mx); v1.y = __expf(v1.y - mx);
    v1.z = __expf(v1.z - mx); v1.w = __expf(v1.w - mx);
    float sm = v0.x + v0.y + v0.z + v0.w + v1.x + v1.y + v1.z + v1.w;
    #pragma unroll
    for (int o = 16; o > 0; o >>= 1)
        sm += __shfl_xor_sync(0xffffffffu, sm, o);
    float inv = 1.f / sm;
    v0.x *= inv; v0.y *= inv; v0.z *= inv; v0.w *= inv;
    v1.x *= inv; v1.y *= inv; v1.z *= inv; v1.w *= inv;
    *(float4*)&row[lane*8]     = v0;
    *(float4*)&row[lane*8 + 4] = v1;
}

// ---------------------------------------------------------------------------
// x[b,i,h*64+d] = sum_j attn[b,h,i,j] * vh[b,j,h*64+d]
// ---------------------------------------------------------------------------
__global__ __launch_bounds__(256) void attnv_kernel()
{
    __shared__ float As[64*68];  // [j][i]
    __shared__ float Vs[64*68];  // [j][d]
    int t  = threadIdx.x;
    int tx = t & 15, ty = t >> 4;
    int i0 = blockIdx.x * 64;
    int bh = blockIdx.y; int b = bh >> 3, h = bh & 7;
    float acc[4][4] = {};

    for (int jc = 0; jc < NN; jc += 64) {
        #pragma unroll
        for (int u = 0; u < 4; u++) {
            int idx = t + u*256;
            int r = idx >> 4, c4 = (idx & 15) * 4;
            float4 a4 = *(const float4*)&g_scores[((b*HH + h)*NN + i0 + r)*NN + jc + c4];
            As[(c4+0)*68 + r] = a4.x; As[(c4+1)*68 + r] = a4.y;
            As[(c4+2)*68 + r] = a4.z; As[(c4+3)*68 + r] = a4.w;
            float4 v4 = *(const float4*)&g_vh[(b*NN + jc + r)*HIDD + h*64 + c4];
            *(float4*)&Vs[r*68 + c4] = v4;
        }
        __syncthreads();
        #pragma unroll 8
        for (int j = 0; j < 64; j++) {
            float4 a4 = *(const float4*)&As[j*68 + ty*4];
            float4 b4 = *(const float4*)&Vs[j*68 + tx*4];
            float av[4] = {a4.x, a4.y, a4.z, a4.w};
            float bv[4] = {b4.x, b4.y, b4.z, b4.w};
            #pragma unroll
            for (int i = 0; i < 4; i++)
                #pragma unroll
                for (int j2 = 0; j2 < 4; j2++)
                    acc[i][j2] += av[i] * bv[j2];
        }
        __syncthreads();
    }
    #pragma unroll
    for (int i = 0; i < 4; i++) {
        float4 o = {acc[i][0], acc[i][1], acc[i][2], acc[i][3]};
        *(float4*)&g_x[(b*NN + i0 + ty*4 + i)*HIDD + h*64 + tx*4] = o;
    }
}

// ---------------------------------------------------------------------------
extern "C" void kernel_launch(void* const* d_in, const int* in_sizes, int n_in,
                              void* d_out, int out_size)
{
    const float* q     = (const float*)d_in[0];
    const float* k     = (const float*)d_in[1];
    const float* v     = (const float*)d_in[2];
    const float* tbias = (const float*)d_in[3];
    const float* fs    = (const float*)d_in[4];
    const float* fo    = (const float*)d_in[5];
    const float* Wq    = (const float*)d_in[6];
    const float* bq    = (const float*)d_in[7];
    const float* Wk    = (const float*)d_in[8];
    const float* bk    = (const float*)d_in[9];
    const float* Wv    = (const float*)d_in[10];
    const float* bv    = (const float*)d_in[11];
    const float* Wo    = (const float*)d_in[12];
    const float* bo    = (const float*)d_in[13];
    const float* fsW1  = (const float*)d_in[14];
    const float* fsb1  = (const float*)d_in[15];
    const float* fsW2  = (const float*)d_in[16];
    const float* fsb2  = (const float*)d_in[17];
    const float* foW1  = (const float*)d_in[18];
    const float* fob1  = (const float*)d_in[19];
    const float* foW2  = (const float*)d_in[20];
    const float* fob2  = (const float*)d_in[21];
    float* out = (float*)d_out;

    float* qh; cudaGetSymbolAddress((void**)&qh, g_qh);
    float* kh; cudaGetSymbolAddress((void**)&kh, g_kh);
    float* vh; cudaGetSymbolAddress((void**)&vh, g_vh);
    float* x;  cudaGetSymbolAddress((void**)&x,  g_x);

    cudaFuncSetAttribute(pair_kernel,
                         cudaFuncAttributeMaxDynamicSharedMemorySize, 51712);

    dim3 gg(8, 64);
    gemm512_kernel<<<gg, 256>>>(q, Wq, bq, qh, 0.125f);
    gemm512_kernel<<<gg, 256>>>(k, Wk, bk, kh, 1.0f);
    gemm512_kernel<<<gg, 256>>>(v, Wv, bv, vh, 1.0f);

    hfeat_kernel<<<(BN*MLPH + 255)/256, 256>>>(fs, fo, fsW1, fsb1, foW1, fob1);

    scores_kernel<<<dim3(4, 4, BB*HH), 256>>>(tbias);

    pair_kernel<<<dim3(4, 16, BB), 256, 51712>>>(fs, fo, fsW1, fsW2, fsb2,
                                                 foW1, foW2, fob2);

    softmax_kernel<<<(BB*HH*NN*32 + 255)/256, 256>>>();

    attnv_kernel<<<dim3(4, BB*HH), 256>>>();

    gemm512_kernel<<<gg, 256>>>(x, Wo, bo, out, 1.0f);
}

// round 10
// speedup vs baseline: 1.4138x; 1.4106x over previous
#include <cuda_runtime.h>
#include <cuda_bf16.h>

#define BB 16
#define NN 256
#define HIDD 512
#define HH 8
#define MLPH 64
#define BN (BB*NN)   // 4096

__device__ __align__(256) float g_qh[BN*HIDD];
__device__ __align__(256) float g_kh[BN*HIDD];
__device__ __align__(256) float g_vh[BN*HIDD];
__device__ __align__(256) float g_x [BN*HIDD];
__device__ __align__(256) float g_scores[BB*HH*NN*NN];
__device__ __align__(256) float g_hiS[BN*MLPH];
__device__ __align__(256) float g_hjS[BN*MLPH];
__device__ __align__(256) float g_hiO[BN*MLPH];
__device__ __align__(256) float g_hjO[BN*MLPH];
__device__ __align__(256) __nv_bfloat16 g_Ahi[BN*HIDD];
__device__ __align__(256) __nv_bfloat16 g_Alo[BN*HIDD];
__device__ __align__(256) __nv_bfloat16 g_WhiT[HIDD*HIDD];
__device__ __align__(256) __nv_bfloat16 g_WloT[HIDD*HIDD];

// ============================ small asm helpers =============================
__device__ __forceinline__ unsigned smem_u32(const void* p) {
    unsigned a;
    asm("{ .reg .u64 t; cvta.to.shared.u64 t, %1; cvt.u32.u64 %0, t; }"
        : "=r"(a) : "l"(p));
    return a;
}
__device__ __forceinline__ void cp16(unsigned dst, const void* src) {
    asm volatile("cp.async.cg.shared.global [%0], [%1], 16;"
                 :: "r"(dst), "l"(src) : "memory");
}
__device__ __forceinline__ void cp_commit() {
    asm volatile("cp.async.commit_group;" ::: "memory");
}
__device__ __forceinline__ void mma_bf16(float* d, const unsigned* a, const unsigned* b) {
    asm volatile("mma.sync.aligned.m16n8k16.row.col.f32.bf16.bf16.f32 "
                 "{%0,%1,%2,%3}, {%4,%5,%6,%7}, {%8,%9}, {%0,%1,%2,%3};"
                 : "+f"(d[0]), "+f"(d[1]), "+f"(d[2]), "+f"(d[3])
                 : "r"(a[0]), "r"(a[1]), "r"(a[2]), "r"(a[3]),
                   "r"(b[0]), "r"(b[1]));
}

// =================== prep: fp32 -> bf16 hi/lo ===============================
__global__ void prep_a_kernel(const float* __restrict__ A,
                              __nv_bfloat16* __restrict__ hi,
                              __nv_bfloat16* __restrict__ lo, int n4)
{
    int i = blockIdx.x * blockDim.x + threadIdx.x;
    if (i >= n4) return;
    float4 a = ((const float4*)A)[i];
    __nv_bfloat16 h0 = __float2bfloat16(a.x), h1 = __float2bfloat16(a.y);
    __nv_bfloat16 h2 = __float2bfloat16(a.z), h3 = __float2bfloat16(a.w);
    __nv_bfloat16 l0 = __float2bfloat16(a.x - __bfloat162float(h0));
    __nv_bfloat16 l1 = __float2bfloat16(a.y - __bfloat162float(h1));
    __nv_bfloat16 l2 = __float2bfloat16(a.z - __bfloat162float(h2));
    __nv_bfloat16 l3 = __float2bfloat16(a.w - __bfloat162float(h3));
    ((__nv_bfloat162*)hi)[i*2]   = __nv_bfloat162(h0, h1);
    ((__nv_bfloat162*)hi)[i*2+1] = __nv_bfloat162(h2, h3);
    ((__nv_bfloat162*)lo)[i*2]   = __nv_bfloat162(l0, l1);
    ((__nv_bfloat162*)lo)[i*2+1] = __nv_bfloat162(l2, l3);
}

// W[k][n] -> WT[n][k] bf16 hi/lo (tiled transpose)
__global__ __launch_bounds__(256) void prep_w_kernel(
    const float* __restrict__ W,
    __nv_bfloat16* __restrict__ hiT, __nv_bfloat16* __restrict__ loT)
{
    __shared__ float tile[32][33];
    int n0 = blockIdx.x*32, k0 = blockIdx.y*32;
    int tx = threadIdx.x & 31, ty = threadIdx.x >> 5;
    for (int r = ty; r < 32; r += 8)
        tile[r][tx] = W[(k0 + r)*512 + n0 + tx];   // tile[k][n]
    __syncthreads();
    for (int rn = ty; rn < 32; rn += 8) {
        float w = tile[tx][rn];
        __nv_bfloat16 h = __float2bfloat16(w);
        __nv_bfloat16 l = __float2bfloat16(w - __bfloat162float(h));
        hiT[(n0 + rn)*512 + k0 + tx] = h;
        loT[(n0 + rn)*512 + k0 + tx] = l;
    }
}

// =================== HMMA GEMM: C = scale*(A@W + bias) ======================
// CTA 128x128, 8 warps (warp tile 64x32), k-chunk 32, 2-stage cp.async.
// Smem per stage: 4 arrays (Ahi,Alo,Bhi,Blo) of 128 rows x 80B = 40960 B.
#define LDAB 80                 // bytes per smem row (32 bf16 + 8 pad)
#define ARR_B (128*LDAB)        // 10240
#define STAGE_B (4*ARR_B)       // 40960
#define SMEM_HM (2*STAGE_B)     // 81920

__global__ __launch_bounds__(256, 1) void gemm_hmma_kernel(
    const __nv_bfloat16* __restrict__ Ahi, const __nv_bfloat16* __restrict__ Alo,
    const __nv_bfloat16* __restrict__ Bhi, const __nv_bfloat16* __restrict__ Blo,
    const float* __restrict__ bias, float* __restrict__ C, float scale)
{
    extern __shared__ char smc[];
    unsigned sb = smem_u32(smc);
    int t = threadIdx.x, lane = t & 31, wid = t >> 5;
    int m0 = blockIdx.y*128, n0 = blockIdx.x*128;
    int wm = (wid >> 2)*64, wn = (wid & 3)*32;
    int g = lane >> 2, tig = lane & 3;

    float acc[4][4][4] = {};

    // stage loader: k-chunk kc (elements), stage s
    auto stage_load = [&](int kc, int s) {
        unsigned base = sb + s*STAGE_B;
        #pragma unroll
        for (int i = 0; i < 2; i++) {
            int idx = t + i*256;
            int r = idx >> 2;
            int cb = (idx & 3)*16;           // byte offset within 64B row payload
            unsigned d = base + r*LDAB + cb;
            int goff = kc + cb/2;            // element offset in k
            cp16(d,            &Ahi[(m0 + r)*512 + goff]);
            cp16(d + ARR_B,    &Alo[(m0 + r)*512 + goff]);
            cp16(d + 2*ARR_B,  &Bhi[(n0 + r)*512 + goff]);
            cp16(d + 3*ARR_B,  &Blo[(n0 + r)*512 + goff]);
        }
        cp_commit();
    };

    stage_load(0, 0);
    stage_load(32, 1);

    for (int kc = 0; kc < 16; kc++) {
        int s = kc & 1;
        if (kc == 15) asm volatile("cp.async.wait_group 0;" ::: "memory");
        else          asm volatile("cp.async.wait_group 1;" ::: "memory");
        __syncthreads();

        const char* stg = smc + s*STAGE_B;

        #pragma unroll
        for (int ks = 0; ks < 32; ks += 16) {
            unsigned ah[4][4], al[4][4], bh[4][2], bl[4][2];
            #pragma unroll
            for (int mi = 0; mi < 4; mi++) {
                int r0 = wm + mi*16 + g;
                int c0 = (ks + 2*tig)*2;     // bytes
                ah[mi][0] = *(const unsigned*)(stg + r0*LDAB + c0);
                ah[mi][1] = *(const unsigned*)(stg + (r0+8)*LDAB + c0);
                ah[mi][2] = *(const unsigned*)(stg + r0*LDAB + c0 + 16);
                ah[mi][3] = *(const unsigned*)(stg + (r0+8)*LDAB + c0 + 16);
                al[mi][0] = *(const unsigned*)(stg + ARR_B + r0*LDAB + c0);
                al[mi][1] = *(const unsigned*)(stg + ARR_B + (r0+8)*LDAB + c0);
                al[mi][2] = *(const unsigned*)(stg + ARR_B + r0*LDAB + c0 + 16);
                al[mi][3] = *(const unsigned*)(stg + ARR_B + (r0+8)*LDAB + c0 + 16);
            }
            #pragma unroll
            for (int ni = 0; ni < 4; ni++) {
                int nr = wn + ni*8 + g;
                int c0 = (ks + 2*tig)*2;
                bh[ni][0] = *(const unsigned*)(stg + 2*ARR_B + nr*LDAB + c0);
                bh[ni][1] = *(const unsigned*)(stg + 2*ARR_B + nr*LDAB + c0 + 16);
                bl[ni][0] = *(const unsigned*)(stg + 3*ARR_B + nr*LDAB + c0);
                bl[ni][1] = *(const unsigned*)(stg + 3*ARR_B + nr*LDAB + c0 + 16);
            }
            #pragma unroll
            for (int mi = 0; mi < 4; mi++)
                #pragma unroll
                for (int ni = 0; ni < 4; ni++) {
                    mma_bf16(acc[mi][ni], ah[mi], bh[ni]);
                    mma_bf16(acc[mi][ni], ah[mi], bl[ni]);
                    mma_bf16(acc[mi][ni], al[mi], bh[ni]);
                }
        }
        __syncthreads();
        if (kc + 2 < 16) stage_load((kc + 2)*32, s);
    }

    // epilogue: d0,d1 -> (row, col..col+1); d2,d3 -> (row+8, ...)
    #pragma unroll
    for (int mi = 0; mi < 4; mi++) {
        int row = m0 + wm + mi*16 + g;
        #pragma unroll
        for (int ni = 0; ni < 4; ni++) {
            int col = n0 + wn + ni*8 + 2*tig;
            float b0 = bias[col], b1 = bias[col + 1];
            float2 o0, o1;
            o0.x = scale*(acc[mi][ni][0] + b0);
            o0.y = scale*(acc[mi][ni][1] + b1);
            o1.x = scale*(acc[mi][ni][2] + b0);
            o1.y = scale*(acc[mi][ni][3] + b1);
            *(float2*)&C[row*512 + col]       = o0;
            *(float2*)&C[(row + 8)*512 + col] = o1;
        }
    }
}

// ============================ hfeat (unchanged) =============================
__global__ void hfeat_kernel(
    const float* __restrict__ fs, const float* __restrict__ fo,
    const float* __restrict__ fsW1, const float* __restrict__ fsb1,
    const float* __restrict__ foW1, const float* __restrict__ fob1)
{
    int idx = blockIdx.x * blockDim.x + threadIdx.x;
    if (idx >= BN*MLPH) return;
    int bn = idx >> 6, m = idx & 63;
    float s_i = fsb1[m], s_j = 0.f, o_i = fob1[m], o_j = 0.f;
    #pragma unroll
    for (int f = 0; f < 8; f++) {
        float vs = fs[bn*8 + f], vo = fo[bn*8 + f];
        s_i += vs * fsW1[f*64 + m];
        s_j += vs * fsW1[(8+f)*64 + m];
        o_i += vo * foW1[f*64 + m];
        o_j += vo * foW1[(8+f)*64 + m];
    }
    g_hiS[idx] = s_i; g_hjS[idx] = s_j; g_hiO[idx] = o_i; g_hjO[idx] = o_j;
}

// ============================ scores (unchanged) ============================
__global__ __launch_bounds__(256) void scores_kernel(const float* __restrict__ tbias)
{
    __shared__ float Qs[64*68];
    __shared__ float Ks[64*68];
    int t  = threadIdx.x;
    int tx = t & 15, ty = t >> 4;
    int j0 = blockIdx.x * 64, i0 = blockIdx.y * 64;
    int bh = blockIdx.z; int b = bh >> 3, h = bh & 7;

    #pragma unroll
    for (int u = 0; u < 4; u++) {
        int idx = t + u*256;
        int r = idx >> 4;
        int c4 = (idx & 15) * 4;
        float4 q4 = *(const float4*)&g_qh[(b*NN + i0 + r)*HIDD + h*64 + c4];
        Qs[(c4+0)*68 + r] = q4.x; Qs[(c4+1)*68 + r] = q4.y;
        Qs[(c4+2)*68 + r] = q4.z; Qs[(c4+3)*68 + r] = q4.w;
        float4 k4 = *(const float4*)&g_kh[(b*NN + j0 + r)*HIDD + h*64 + c4];
        Ks[(c4+0)*68 + r] = k4.x; Ks[(c4+1)*68 + r] = k4.y;
        Ks[(c4+2)*68 + r] = k4.z; Ks[(c4+3)*68 + r] = k4.w;
    }
    __syncthreads();

    float acc[4][4] = {};
    #pragma unroll 8
    for (int k = 0; k < 64; k++) {
        float4 a4 = *(const float4*)&Qs[k*68 + ty*4];
        float4 b4 = *(const float4*)&Ks[k*68 + tx*4];
        float av[4] = {a4.x, a4.y, a4.z, a4.w};
        float bv[4] = {b4.x, b4.y, b4.z, b4.w};
        #pragma unroll
        for (int i = 0; i < 4; i++)
            #pragma unroll
            for (int j = 0; j < 4; j++)
                acc[i][j] += av[i] * bv[j];
    }

    #pragma unroll
    for (int i = 0; i < 4; i++) {
        int gi = i0 + ty*4 + i;
        int base = ((b*HH + h)*NN + gi)*NN + j0 + tx*4;
        float4 bb = *(const float4*)&tbias[base];
        float4 o;
        o.x = acc[i][0] + bb.x; o.y = acc[i][1] + bb.y;
        o.z = acc[i][2] + bb.z; o.w = acc[i][3] + bb.w;
        *(float4*)&g_scores[base] = o;
    }
}

// ============================ pair (unchanged) ==============================
__global__ __launch_bounds__(256) void pair_kernel(
    const float* __restrict__ fs, const float* __restrict__ fo,
    const float* __restrict__ fsW1, const float* __restrict__ fsW2, const float* __restrict__ fsb2,
    const float* __restrict__ foW1, const float* __restrict__ foW2, const float* __restrict__ fob2)
{
    extern __shared__ float sm[];
    float* hiS = sm;
    float* hiO = hiS + 16*68;
    float* hjS = hiO + 16*68;
    float* hjO = hjS + 64*68;
    float* WcS = hjO + 64*68;
    float* WcO = WcS + 512;
    float* W2S = WcO + 512;
    float* W2O = W2S + 512;

    int t  = threadIdx.x;
    int b  = blockIdx.z;
    int i0 = blockIdx.y * 16;
    int j0 = blockIdx.x * 64;

    {
        int r = t >> 4, c4 = (t & 15) * 4;
        *(float4*)&hiS[r*68 + c4] = *(const float4*)&g_hiS[(b*NN + i0 + r)*64 + c4];
        *(float4*)&hiO[r*68 + c4] = *(const float4*)&g_hiO[(b*NN + i0 + r)*64 + c4];
    }
    #pragma unroll
    for (int u = 0; u < 4; u++) {
        int idx = t + u*256;
        int jr = idx >> 4, c4 = (idx & 15) * 4;
        float4 v = *(const float4*)&g_hjS[(b*NN + j0 + jr)*64 + c4];
        hjS[(c4+0)*68 + jr] = v.x; hjS[(c4+1)*68 + jr] = v.y;
        hjS[(c4+2)*68 + jr] = v.z; hjS[(c4+3)*68 + jr] = v.w;
        float4 w = *(const float4*)&g_hjO[(b*NN + j0 + jr)*64 + c4];
        hjO[(c4+0)*68 + jr] = w.x; hjO[(c4+1)*68 + jr] = w.y;
        hjO[(c4+2)*68 + jr] = w.z; hjO[(c4+3)*68 + jr] = w.w;
    }
    if (t < 128) {
        *(float4*)&WcS[t*4] = *(const float4*)&fsW1[16*64 + t*4];
        *(float4*)&WcO[t*4] = *(const float4*)&foW1[16*64 + t*4];
        *(float4*)&W2S[t*4] = *(const float4*)&fsW2[t*4];
        *(float4*)&W2O[t*4] = *(const float4*)&foW2[t*4];
    }
    __syncthreads();

    int ti = t >> 4;
    int tj = t & 15;
    int i  = i0 + ti;

    float dS[4][8], dO[4][8];
    {
        float fiS[8], fiO[8];
        #pragma unroll
        for (int f = 0; f < 8; f++) {
            fiS[f] = fs[(b*NN + i)*8 + f];
            fiO[f] = fo[(b*NN + i)*8 + f];
        }
        #pragma unroll
        for (int jj = 0; jj < 4; jj++) {
            int j = j0 + tj*4 + jj;
            #pragma unroll
            for (int f = 0; f < 8; f++) {
                dS[jj][f] = fabsf(fiS[f] - fs[(b*NN + j)*8 + f]);
                dO[jj][f] = fabsf(fiO[f] - fo[(b*NN + j)*8 + f]);
            }
        }
    }

    float p[4][8];
    #pragma unroll
    for (int jj = 0; jj < 4; jj++)
        #pragma unroll
        for (int hh = 0; hh < 8; hh++)
            p[jj][hh] = fsb2[hh] + fob2[hh];

    for (int m = 0; m < 64; m++) {
        float aS = hiS[ti*68 + m];
        float aO = hiO[ti*68 + m];
        float4 hS4 = *(const float4*)&hjS[m*68 + tj*4];
        float4 hO4 = *(const float4*)&hjO[m*68 + tj*4];
        float uS[4] = {aS + hS4.x, aS + hS4.y, aS + hS4.z, aS + hS4.w};
        float uO[4] = {aO + hO4.x, aO + hO4.y, aO + hO4.z, aO + hO4.w};
        #pragma unroll
        for (int f = 0; f < 8; f++) {
            float wS = WcS[f*64 + m], wO = WcO[f*64 + m];
            #pragma unroll
            for (int jj = 0; jj < 4; jj++) {
                uS[jj] += dS[jj][f] * wS;
                uO[jj] += dO[jj][f] * wO;
            }
        }
        #pragma unroll
        for (int jj = 0; jj < 4; jj++) {
            uS[jj] = fmaxf(uS[jj], 0.f);
            uO[jj] = fmaxf(uO[jj], 0.f);
        }
        #pragma unroll
        for (int hh = 0; hh < 8; hh++) {
            float w2s = W2S[m*8 + hh], w2o = W2O[m*8 + hh];
            #pragma unroll
            for (int jj = 0; jj < 4; jj++)
                p[jj][hh] += uS[jj]*w2s + uO[jj]*w2o;
        }
    }

    #pragma unroll
    for (int hh = 0; hh < 8; hh++) {
        float* sp = &g_scores[((b*HH + hh)*NN + i)*NN + j0 + tj*4];
        float4 s = *(float4*)sp;
        s.x += 0.1f * p[0][hh];
        s.y += 0.1f * p[1][hh];
        s.z += 0.1f * p[2][hh];
        s.w += 0.1f * p[3][hh];
        *(float4*)sp = s;
    }
}

// ============================ softmax (unchanged) ===========================
__global__ void softmax_kernel()
{
    int warp = (blockIdx.x * blockDim.x + threadIdx.x) >> 5;
    int lane = threadIdx.x & 31;
    if (warp >= BB*HH*NN) return;
    float* row = &g_scores[(size_t)warp * NN];
    float4 v0 = *(float4*)&row[lane*8];
    float4 v1 = *(float4*)&row[lane*8 + 4];
    float mx = fmaxf(fmaxf(fmaxf(v0.x, v0.y), fmaxf(v0.z, v0.w)),
                     fmaxf(fmaxf(v1.x, v1.y), fmaxf(v1.z, v1.w)));
    #pragma unroll
    for (int o = 16; o > 0; o >>= 1)
        mx = fmaxf(mx, __shfl_xor_sync(0xffffffffu, mx, o));
    v0.x = __expf(v0.x - mx); v0.y = __expf(v0.y - mx);
    v0.z = __expf(v0.z - mx); v0.w = __expf(v0.w - mx);
    v1.x = __expf(v1.x - mx); v1.y = __expf(v1.y - mx);
    v1.z = __expf(v1.z - mx); v1.w = __expf(v1.w - mx);
    float sm = v0.x + v0.y + v0.z + v0.w + v1.x + v1.y + v1.z + v1.w;
    #pragma unroll
    for (int o = 16; o > 0; o >>= 1)
        sm += __shfl_xor_sync(0xffffffffu, sm, o);
    float inv = 1.f / sm;
    v0.x *= inv; v0.y *= inv; v0.z *= inv; v0.w *= inv;
    v1.x *= inv; v1.y *= inv; v1.z *= inv; v1.w *= inv;
    *(float4*)&row[lane*8]     = v0;
    *(float4*)&row[lane*8 + 4] = v1;
}

// ============================ attnv (unchanged) =============================
__global__ __launch_bounds__(256) void attnv_kernel()
{
    __shared__ float As[64*68];
    __shared__ float Vs[64*68];
    int t  = threadIdx.x;
    int tx = t & 15, ty = t >> 4;
    int i0 = blockIdx.x * 64;
    int bh = blockIdx.y; int b = bh >> 3, h = bh & 7;
    float acc[4][4] = {};

    for (int jc = 0; jc < NN; jc += 64) {
        #pragma unroll
        for (int u = 0; u < 4; u++) {
            int idx = t + u*256;
            int r = idx >> 4, c4 = (idx & 15) * 4;
            float4 a4 = *(const float4*)&g_scores[((b*HH + h)*NN + i0 + r)*NN + jc + c4];
            As[(c4+0)*68 + r] = a4.x; As[(c4+1)*68 + r] = a4.y;
            As[(c4+2)*68 + r] = a4.z; As[(c4+3)*68 + r] = a4.w;
            float4 v4 = *(const float4*)&g_vh[(b*NN + jc + r)*HIDD + h*64 + c4];
            *(float4*)&Vs[r*68 + c4] = v4;
        }
        __syncthreads();
        #pragma unroll 8
        for (int j = 0; j < 64; j++) {
            float4 a4 = *(const float4*)&As[j*68 + ty*4];
            float4 b4 = *(const float4*)&Vs[j*68 + tx*4];
            float av[4] = {a4.x, a4.y, a4.z, a4.w};
            float bv[4] = {b4.x, b4.y, b4.z, b4.w};
            #pragma unroll
            for (int i = 0; i < 4; i++)
                #pragma unroll
                for (int j2 = 0; j2 < 4; j2++)
                    acc[i][j2] += av[i] * bv[j2];
        }
        __syncthreads();
    }
    #pragma unroll
    for (int i = 0; i < 4; i++) {
        float4 o = {acc[i][0], acc[i][1], acc[i][2], acc[i][3]};
        *(float4*)&g_x[(b*NN + i0 + ty*4 + i)*HIDD + h*64 + tx*4] = o;
    }
}

// ===========================================================================
extern "C" void kernel_launch(void* const* d_in, const int* in_sizes, int n_in,
                              void* d_out, int out_size)
{
    const float* q     = (const float*)d_in[0];
    const float* k     = (const float*)d_in[1];
    const float* v     = (const float*)d_in[2];
    const float* tbias = (const float*)d_in[3];
    const float* fs    = (const float*)d_in[4];
    const float* fo    = (const float*)d_in[5];
    const float* Wq    = (const float*)d_in[6];
    const float* bq    = (const float*)d_in[7];
    const float* Wk    = (const float*)d_in[8];
    const float* bk    = (const float*)d_in[9];
    const float* Wv    = (const float*)d_in[10];
    const float* bv    = (const float*)d_in[11];
    const float* Wo    = (const float*)d_in[12];
    const float* bo    = (const float*)d_in[13];
    const float* fsW1  = (const float*)d_in[14];
    const float* fsb1  = (const float*)d_in[15];
    const float* fsW2  = (const float*)d_in[16];
    const float* fsb2  = (const float*)d_in[17];
    const float* foW1  = (const float*)d_in[18];
    const float* fob1  = (const float*)d_in[19];
    const float* foW2  = (const float*)d_in[20];
    const float* fob2  = (const float*)d_in[21];
    float* out = (float*)d_out;

    float* qh; cudaGetSymbolAddress((void**)&qh, g_qh);
    float* kh; cudaGetSymbolAddress((void**)&kh, g_kh);
    float* vh; cudaGetSymbolAddress((void**)&vh, g_vh);
    float* x;  cudaGetSymbolAddress((void**)&x,  g_x);
    __nv_bfloat16* Ahi;  cudaGetSymbolAddress((void**)&Ahi,  g_Ahi);
    __nv_bfloat16* Alo;  cudaGetSymbolAddress((void**)&Alo,  g_Alo);
    __nv_bfloat16* WhiT; cudaGetSymbolAddress((void**)&WhiT, g_WhiT);
    __nv_bfloat16* WloT; cudaGetSymbolAddress((void**)&WloT, g_WloT);

    cudaFuncSetAttribute(pair_kernel,
                         cudaFuncAttributeMaxDynamicSharedMemorySize, 51712);
    cudaFuncSetAttribute(gemm_hmma_kernel,
                         cudaFuncAttributeMaxDynamicSharedMemorySize, SMEM_HM);

    const int n4 = BN*HIDD/4;
    dim3 gw(16, 16);
    dim3 ghm(4, 32);

    // Q projection (scale folds 1/sqrt(dk))
    prep_a_kernel<<<(n4 + 255)/256, 256>>>(q, Ahi, Alo, n4);
    prep_w_kernel<<<gw, 256>>>(Wq, WhiT, WloT);
    gemm_hmma_kernel<<<ghm, 256, SMEM_HM>>>(Ahi, Alo, WhiT, WloT, bq, qh, 0.125f);
    // K projection
    prep_a_kernel<<<(n4 + 255)/256, 256>>>(k, Ahi, Alo, n4);
    prep_w_kernel<<<gw, 256>>>(Wk, WhiT, WloT);
    gemm_hmma_kernel<<<ghm, 256, SMEM_HM>>>(Ahi, Alo, WhiT, WloT, bk, kh, 1.0f);
    // V projection
    prep_a_kernel<<<(n4 + 255)/256, 256>>>(v, Ahi, Alo, n4);
    prep_w_kernel<<<gw, 256>>>(Wv, WhiT, WloT);
    gemm_hmma_kernel<<<ghm, 256, SMEM_HM>>>(Ahi, Alo, WhiT, WloT, bv, vh, 1.0f);

    hfeat_kernel<<<(BN*MLPH + 255)/256, 256>>>(fs, fo, fsW1, fsb1, foW1, fob1);

    scores_kernel<<<dim3(4, 4, BB*HH), 256>>>(tbias);

    pair_kernel<<<dim3(4, 16, BB), 256, 51712>>>(fs, fo, fsW1, fsW2, fsb2,
                                                 foW1, foW2, fob2);

    softmax_kernel<<<(BB*HH*NN*32 + 255)/256, 256>>>();

    attnv_kernel<<<dim3(4, BB*HH), 256>>>();

    // Output projection
    prep_a_kernel<<<(n4 + 255)/256, 256>>>(x, Ahi, Alo, n4);
    prep_w_kernel<<<gw, 256>>>(Wo, WhiT, WloT);
    gemm_hmma_kernel<<<ghm, 256, SMEM_HM>>>(Ahi, Alo, WhiT, WloT, bo, out, 1.0f);
}

// round 15
// speedup vs baseline: 1.6986x; 1.2014x over previous
#include <cuda_runtime.h>
#include <cuda_bf16.h>

#define BB 16
#define NN 256
#define HIDD 512
#define HH 8
#define MLPH 64
#define BN (BB*NN)   // 4096

__device__ __align__(256) float g_qh[BN*HIDD];
__device__ __align__(256) float g_kh[BN*HIDD];
__device__ __align__(256) float g_vh[BN*HIDD];
__device__ __align__(256) float g_x [BN*HIDD];
__device__ __align__(256) float g_scores[BB*HH*NN*NN];
__device__ __align__(256) float g_hiS[BN*MLPH];
__device__ __align__(256) float g_hiO[BN*MLPH];
__device__ __align__(256) __nv_bfloat16 g_Ahi[BN*HIDD];
__device__ __align__(256) __nv_bfloat16 g_Alo[BN*HIDD];
__device__ __align__(256) __nv_bfloat16 g_WhiT[HIDD*HIDD];
__device__ __align__(256) __nv_bfloat16 g_WloT[HIDD*HIDD];

// ============================ small asm helpers =============================
__device__ __forceinline__ unsigned smem_u32(const void* p) {
    unsigned a;
    asm("{ .reg .u64 t; cvta.to.shared.u64 t, %1; cvt.u32.u64 %0, t; }"
        : "=r"(a) : "l"(p));
    return a;
}
__device__ __forceinline__ void cp16(unsigned dst, const void* src) {
    asm volatile("cp.async.cg.shared.global [%0], [%1], 16;"
                 :: "r"(dst), "l"(src) : "memory");
}
__device__ __forceinline__ void cp_commit() {
    asm volatile("cp.async.commit_group;" ::: "memory");
}
__device__ __forceinline__ void mma_bf16(float* d, const unsigned* a, const unsigned* b) {
    asm volatile("mma.sync.aligned.m16n8k16.row.col.f32.bf16.bf16.f32 "
                 "{%0,%1,%2,%3}, {%4,%5,%6,%7}, {%8,%9}, {%0,%1,%2,%3};"
                 : "+f"(d[0]), "+f"(d[1]), "+f"(d[2]), "+f"(d[3])
                 : "r"(a[0]), "r"(a[1]), "r"(a[2]), "r"(a[3]),
                   "r"(b[0]), "r"(b[1]));
}
// pack two floats into bf16x2 (lo half = first arg)
__device__ __forceinline__ unsigned pk(float a, float b) {
    __nv_bfloat162 v = __floats2bfloat162_rn(a, b);
    return *(unsigned*)&v;
}
__device__ __forceinline__ float resid(float x) {
    return x - __bfloat162float(__float2bfloat16_rn(x));
}
__device__ __forceinline__ unsigned pklo(float a, float b) {
    return pk(resid(a), resid(b));
}

// =================== prep: fp32 -> bf16 hi/lo ===============================
__global__ void prep_a_kernel(const float* __restrict__ A,
                              __nv_bfloat16* __restrict__ hi,
                              __nv_bfloat16* __restrict__ lo, int n4)
{
    int i = blockIdx.x * blockDim.x + threadIdx.x;
    if (i >= n4) return;
    float4 a = ((const float4*)A)[i];
    __nv_bfloat16 h0 = __float2bfloat16(a.x), h1 = __float2bfloat16(a.y);
    __nv_bfloat16 h2 = __float2bfloat16(a.z), h3 = __float2bfloat16(a.w);
    __nv_bfloat16 l0 = __float2bfloat16(a.x - __bfloat162float(h0));
    __nv_bfloat16 l1 = __float2bfloat16(a.y - __bfloat162float(h1));
    __nv_bfloat16 l2 = __float2bfloat16(a.z - __bfloat162float(h2));
    __nv_bfloat16 l3 = __float2bfloat16(a.w - __bfloat162float(h3));
    ((__nv_bfloat162*)hi)[i*2]   = __nv_bfloat162(h0, h1);
    ((__nv_bfloat162*)hi)[i*2+1] = __nv_bfloat162(h2, h3);
    ((__nv_bfloat162*)lo)[i*2]   = __nv_bfloat162(l0, l1);
    ((__nv_bfloat162*)lo)[i*2+1] = __nv_bfloat162(l2, l3);
}

// W[k][n] -> WT[n][k] bf16 hi/lo (tiled transpose)
__global__ __launch_bounds__(256) void prep_w_kernel(
    const float* __restrict__ W,
    __nv_bfloat16* __restrict__ hiT, __nv_bfloat16* __restrict__ loT)
{
    __shared__ float tile[32][33];
    int n0 = blockIdx.x*32, k0 = blockIdx.y*32;
    int tx = threadIdx.x & 31, ty = threadIdx.x >> 5;
    for (int r = ty; r < 32; r += 8)
        tile[r][tx] = W[(k0 + r)*512 + n0 + tx];   // tile[k][n]
    __syncthreads();
    for (int rn = ty; rn < 32; rn += 8) {
        float w = tile[tx][rn];
        __nv_bfloat16 h = __float2bfloat16(w);
        __nv_bfloat16 l = __float2bfloat16(w - __bfloat162float(h));
        hiT[(n0 + rn)*512 + k0 + tx] = h;
        loT[(n0 + rn)*512 + k0 + tx] = l;
    }
}

// =================== HMMA GEMM: C = scale*(A@W + bias) ======================
#define LDAB 80                 // bytes per smem row (32 bf16 + 8 pad)
#define ARR_B (128*LDAB)        // 10240
#define STAGE_B (4*ARR_B)       // 40960
#define SMEM_HM (2*STAGE_B)     // 81920

__global__ __launch_bounds__(256, 1) void gemm_hmma_kernel(
    const __nv_bfloat16* __restrict__ Ahi, const __nv_bfloat16* __restrict__ Alo,
    const __nv_bfloat16* __restrict__ Bhi, const __nv_bfloat16* __restrict__ Blo,
    const float* __restrict__ bias, float* __restrict__ C, float scale)
{
    extern __shared__ char smc[];
    unsigned sb = smem_u32(smc);
    int t = threadIdx.x, lane = t & 31, wid = t >> 5;
    int m0 = blockIdx.y*128, n0 = blockIdx.x*128;
    int wm = (wid >> 2)*64, wn = (wid & 3)*32;
    int g = lane >> 2, tig = lane & 3;

    float acc[4][4][4] = {};

    auto stage_load = [&](int kc, int s) {
        unsigned base = sb + s*STAGE_B;
        #pragma unroll
        for (int i = 0; i < 2; i++) {
            int idx = t + i*256;
            int r = idx >> 2;
            int cb = (idx & 3)*16;
            unsigned d = base + r*LDAB + cb;
            int goff = kc + cb/2;
            cp16(d,            &Ahi[(m0 + r)*512 + goff]);
            cp16(d + ARR_B,    &Alo[(m0 + r)*512 + goff]);
            cp16(d + 2*ARR_B,  &Bhi[(n0 + r)*512 + goff]);
            cp16(d + 3*ARR_B,  &Blo[(n0 + r)*512 + goff]);
        }
        cp_commit();
    };

    stage_load(0, 0);
    stage_load(32, 1);

    #pragma unroll 1
    for (int kc = 0; kc < 16; kc++) {
        int s = kc & 1;
        if (kc == 15) asm volatile("cp.async.wait_group 0;" ::: "memory");
        else          asm volatile("cp.async.wait_group 1;" ::: "memory");
        __syncthreads();

        const char* stg = smc + s*STAGE_B;

        #pragma unroll
        for (int ks = 0; ks < 32; ks += 16) {
            unsigned ah[4][4], al[4][4], bh[4][2], bl[4][2];
            #pragma unroll
            for (int mi = 0; mi < 4; mi++) {
                int r0 = wm + mi*16 + g;
                int c0 = (ks + 2*tig)*2;
                ah[mi][0] = *(const unsigned*)(stg + r0*LDAB + c0);
                ah[mi][1] = *(const unsigned*)(stg + (r0+8)*LDAB + c0);
                ah[mi][2] = *(const unsigned*)(stg + r0*LDAB + c0 + 16);
                ah[mi][3] = *(const unsigned*)(stg + (r0+8)*LDAB + c0 + 16);
                al[mi][0] = *(const unsigned*)(stg + ARR_B + r0*LDAB + c0);
                al[mi][1] = *(const unsigned*)(stg + ARR_B + (r0+8)*LDAB + c0);
                al[mi][2] = *(const unsigned*)(stg + ARR_B + r0*LDAB + c0 + 16);
                al[mi][3] = *(const unsigned*)(stg + ARR_B + (r0+8)*LDAB + c0 + 16);
            }
            #pragma unroll
            for (int ni = 0; ni < 4; ni++) {
                int nr = wn + ni*8 + g;
                int c0 = (ks + 2*tig)*2;
                bh[ni][0] = *(const unsigned*)(stg + 2*ARR_B + nr*LDAB + c0);
                bh[ni][1] = *(const unsigned*)(stg + 2*ARR_B + nr*LDAB + c0 + 16);
                bl[ni][0] = *(const unsigned*)(stg + 3*ARR_B + nr*LDAB + c0);
                bl[ni][1] = *(const unsigned*)(stg + 3*ARR_B + nr*LDAB + c0 + 16);
            }
            #pragma unroll
            for (int mi = 0; mi < 4; mi++)
                #pragma unroll
                for (int ni = 0; ni < 4; ni++) {
                    mma_bf16(acc[mi][ni], ah[mi], bh[ni]);
                    mma_bf16(acc[mi][ni], ah[mi], bl[ni]);
                    mma_bf16(acc[mi][ni], al[mi], bh[ni]);
                }
        }
        __syncthreads();
        if (kc + 2 < 16) stage_load((kc + 2)*32, s);
    }

    #pragma unroll
    for (int mi = 0; mi < 4; mi++) {
        int row = m0 + wm + mi*16 + g;
        #pragma unroll
        for (int ni = 0; ni < 4; ni++) {
            int col = n0 + wn + ni*8 + 2*tig;
            float b0 = bias[col], b1 = bias[col + 1];
            float2 o0, o1;
            o0.x = scale*(acc[mi][ni][0] + b0);
            o0.y = scale*(acc[mi][ni][1] + b1);
            o1.x = scale*(acc[mi][ni][2] + b0);
            o1.y = scale*(acc[mi][ni][3] + b1);
            *(float2*)&C[row*512 + col]       = o0;
            *(float2*)&C[(row + 8)*512 + col] = o1;
        }
    }
}

// ============================ hfeat: hi = feat@Wa + b1 ======================
__global__ void hfeat_kernel(
    const float* __restrict__ fs, const float* __restrict__ fo,
    const float* __restrict__ fsW1, const float* __restrict__ fsb1,
    const float* __restrict__ foW1, const float* __restrict__ fob1)
{
    int idx = blockIdx.x * blockDim.x + threadIdx.x;
    if (idx >= BN*MLPH) return;
    int bn = idx >> 6, m = idx & 63;
    float s_i = fsb1[m], o_i = fob1[m];
    #pragma unroll
    for (int f = 0; f < 8; f++) {
        float vs = fs[bn*8 + f], vo = fo[bn*8 + f];
        s_i += vs * fsW1[f*64 + m];
        o_i += vo * foW1[f*64 + m];
    }
    g_hiS[idx] = s_i; g_hiO[idx] = o_i;
}

// ============================ scores (unchanged) ============================
__global__ __launch_bounds__(256) void scores_kernel(const float* __restrict__ tbias)
{
    __shared__ float Qs[64*68];
    __shared__ float Ks[64*68];
    int t  = threadIdx.x;
    int tx = t & 15, ty = t >> 4;
    int j0 = blockIdx.x * 64, i0 = blockIdx.y * 64;
    int bh = blockIdx.z; int b = bh >> 3, h = bh & 7;

    #pragma unroll
    for (int u = 0; u < 4; u++) {
        int idx = t + u*256;
        int r = idx >> 4;
        int c4 = (idx & 15) * 4;
        float4 q4 = *(const float4*)&g_qh[(b*NN + i0 + r)*HIDD + h*64 + c4];
        Qs[(c4+0)*68 + r] = q4.x; Qs[(c4+1)*68 + r] = q4.y;
        Qs[(c4+2)*68 + r] = q4.z; Qs[(c4+3)*68 + r] = q4.w;
        float4 k4 = *(const float4*)&g_kh[(b*NN + j0 + r)*HIDD + h*64 + c4];
        Ks[(c4+0)*68 + r] = k4.x; Ks[(c4+1)*68 + r] = k4.y;
        Ks[(c4+2)*68 + r] = k4.z; Ks[(c4+3)*68 + r] = k4.w;
    }
    __syncthreads();

    float acc[4][4] = {};
    #pragma unroll 8
    for (int k = 0; k < 64; k++) {
        float4 a4 = *(const float4*)&Qs[k*68 + ty*4];
        float4 b4 = *(const float4*)&Ks[k*68 + tx*4];
        float av[4] = {a4.x, a4.y, a4.z, a4.w};
        float bv[4] = {b4.x, b4.y, b4.z, b4.w};
        #pragma unroll
        for (int i = 0; i < 4; i++)
            #pragma unroll
            for (int j = 0; j < 4; j++)
                acc[i][j] += av[i] * bv[j];
    }

    #pragma unroll
    for (int i = 0; i < 4; i++) {
        int gi = i0 + ty*4 + i;
        int base = ((b*HH + h)*NN + gi)*NN + j0 + tx*4;
        float4 bb = *(const float4*)&tbias[base];
        float4 o;
        o.x = acc[i][0] + bb.x; o.y = acc[i][1] + bb.y;
        o.z = acc[i][2] + bb.z; o.w = acc[i][3] + bb.w;
        *(float4*)&g_scores[base] = o;
    }
}

// =================== pair bias via back-to-back HMMA ========================
// CTA = (i-group of 16, b). 8 warps; warp w covers j = jh*128 + w*16 + [0,16).
// L1: [ |fi-fj| || fj ] (16j x 16k) @ [Wc;Wb] (16k x 64m), acc preloaded with
//     hi_i[m] (fp32, includes b1). 3-term hi/lo.
// L2: relu(U) (16j x 64m) @ W2 (64m x 8h), acc preloaded with b2. 2-term (B lo).
// scores[b,h,i,j] += 0.1 * (pS + pO).
// NOTE: outer ii/jh loops are #pragma unroll 1 to bound codegen size
// (suspected ptxas wallclock blowup -> container timeout in R12/R13).
#define PAIR_SMEMF 12288   // floats
#define FB1(ml,nt,r,hl) fb1[((((ml)*8+(nt))*2+(r))*2+(hl))*32 + lane]
#define FB2(ml,ks,r,hl) fb2[((((ml)*4+(ks))*2+(r))*2+(hl))*32 + lane]

__global__ __launch_bounds__(256) void pair_mma_kernel(
    const float* __restrict__ fs, const float* __restrict__ fo,
    const float* __restrict__ fsW1, const float* __restrict__ fsW2, const float* __restrict__ fsb2,
    const float* __restrict__ foW1, const float* __restrict__ foW2, const float* __restrict__ fob2)
{
    extern __shared__ float ps[];
    float* sW1 = ps;                    // [ml][16][64] rows 8..23 of W1
    float* sW2 = ps + 2048;             // [ml][64][8]
    float* sF  = ps + 3072;             // [ml][256][8]
    float* sHi = ps + 7168;             // [ml][16][64]
    unsigned* fb1 = (unsigned*)(ps + 9216);   // 2048 u32
    unsigned* fb2 = (unsigned*)(ps + 11264);  // 1024 u32

    int t = threadIdx.x, lane = t & 31, w = t >> 5;
    int g = lane >> 2;
    int tig = lane & 3;
    int ig = blockIdx.x, b = blockIdx.y;
    int i0 = ig*16;

    // ---- stage ----
    for (int idx = t; idx < 1024; idx += 256) {
        int r = idx >> 6, c = idx & 63;
        sW1[idx]        = fsW1[(8+r)*64 + c];
        sW1[1024+idx]   = foW1[(8+r)*64 + c];
        sHi[idx]        = g_hiS[(b*NN + i0 + r)*64 + c];
        sHi[1024+idx]   = g_hiO[(b*NN + i0 + r)*64 + c];
    }
    for (int idx = t; idx < 512; idx += 256) {
        sW2[idx]       = fsW2[idx];
        sW2[512+idx]   = foW2[idx];
    }
    for (int idx = t; idx < 2048; idx += 256) {
        sF[idx]        = fs[b*NN*8 + idx];
        sF[2048+idx]   = fo[b*NN*8 + idx];
    }
    __syncthreads();

    // ---- build per-lane weight fragments (identical across warps) ----
    if (w == 0) {
        #pragma unroll
        for (int ml = 0; ml < 2; ml++)
            #pragma unroll
            for (int nt = 0; nt < 8; nt++) {
                int n = nt*8 + g;
                const float* W = sW1 + ml*1024;
                float w00 = W[(2*tig+8)*64 + n], w01 = W[(2*tig+9)*64 + n];
                float w10 = W[(2*tig)*64 + n],   w11 = W[(2*tig+1)*64 + n];
                FB1(ml,nt,0,0) = pk(w00, w01);
                FB1(ml,nt,0,1) = pklo(w00, w01);
                FB1(ml,nt,1,0) = pk(w10, w11);
                FB1(ml,nt,1,1) = pklo(w10, w11);
            }
    } else if (w == 1) {
        #pragma unroll
        for (int ml = 0; ml < 2; ml++)
            #pragma unroll
            for (int ks = 0; ks < 4; ks++) {
                const float* W = sW2 + ml*512;
                float w00 = W[(16*ks+2*tig)*8 + g],   w01 = W[(16*ks+2*tig+1)*8 + g];
                float w10 = W[(16*ks+2*tig+8)*8 + g], w11 = W[(16*ks+2*tig+9)*8 + g];
                FB2(ml,ks,0,0) = pk(w00, w01);
                FB2(ml,ks,0,1) = pklo(w00, w01);
                FB2(ml,ks,1,0) = pk(w10, w11);
                FB2(ml,ks,1,1) = pklo(w10, w11);
            }
    }
    __syncthreads();

    float b2r[2][2];
    b2r[0][0] = fsb2[2*tig]; b2r[0][1] = fsb2[2*tig+1];
    b2r[1][0] = fob2[2*tig]; b2r[1][1] = fob2[2*tig+1];

    float accL1[8][4];
    unsigned upk[8][2];

    #pragma unroll 1
    for (int jh = 0; jh < 2; jh++) {
        int jbase = jh*128 + w*16;
        // per-MLP fj residents: values + a2/a3 fragments
        float fjv[2][2][2];
        unsigned fa2h[2], fa3h[2], fa2l[2], fa3l[2];
        #pragma unroll
        for (int ml = 0; ml < 2; ml++) {
            const float* F = sF + ml*2048;
            float f00 = F[(jbase+g)*8 + 2*tig],   f01 = F[(jbase+g)*8 + 2*tig+1];
            float f10 = F[(jbase+g+8)*8 + 2*tig], f11 = F[(jbase+g+8)*8 + 2*tig+1];
            fjv[ml][0][0] = f00; fjv[ml][0][1] = f01;
            fjv[ml][1][0] = f10; fjv[ml][1][1] = f11;
            fa2h[ml] = pk(f00, f01); fa2l[ml] = pklo(f00, f01);
            fa3h[ml] = pk(f10, f11); fa3l[ml] = pklo(f10, f11);
        }

        #pragma unroll 1
        for (int ii = 0; ii < 16; ii++) {
            float pacc[4] = {0.f, 0.f, 0.f, 0.f};
            #pragma unroll
            for (int ml = 0; ml < 2; ml++) {
                const float* F = sF + ml*2048;
                float fi0 = F[(i0+ii)*8 + 2*tig], fi1 = F[(i0+ii)*8 + 2*tig+1];
                float d00 = fabsf(fi0 - fjv[ml][0][0]), d01 = fabsf(fi1 - fjv[ml][0][1]);
                float d10 = fabsf(fi0 - fjv[ml][1][0]), d11 = fabsf(fi1 - fjv[ml][1][1]);
                unsigned ah[4], al[4];
                ah[0] = pk(d00, d01);  ah[1] = pk(d10, d11);
                ah[2] = fa2h[ml];      ah[3] = fa3h[ml];
                al[0] = pklo(d00, d01); al[1] = pklo(d10, d11);
                al[2] = fa2l[ml];      al[3] = fa3l[ml];

                const float* Hi = sHi + ml*1024 + ii*64;
                #pragma unroll
                for (int nt = 0; nt < 8; nt++) {
                    float h0 = Hi[8*nt + 2*tig], h1 = Hi[8*nt + 2*tig + 1];
                    accL1[nt][0] = h0; accL1[nt][1] = h1;
                    accL1[nt][2] = h0; accL1[nt][3] = h1;
                    unsigned bh[2] = {FB1(ml,nt,0,0), FB1(ml,nt,1,0)};
                    unsigned bl[2] = {FB1(ml,nt,0,1), FB1(ml,nt,1,1)};
                    mma_bf16(accL1[nt], ah, bh);
                    mma_bf16(accL1[nt], al, bh);
                    mma_bf16(accL1[nt], ah, bl);
                }
                #pragma unroll
                for (int nt = 0; nt < 8; nt++) {
                    upk[nt][0] = pk(fmaxf(accL1[nt][0], 0.f), fmaxf(accL1[nt][1], 0.f));
                    upk[nt][1] = pk(fmaxf(accL1[nt][2], 0.f), fmaxf(accL1[nt][3], 0.f));
                }
                float acc2[4];
                acc2[0] = b2r[ml][0]; acc2[1] = b2r[ml][1];
                acc2[2] = b2r[ml][0]; acc2[3] = b2r[ml][1];
                #pragma unroll
                for (int ks = 0; ks < 4; ks++) {
                    unsigned a2[4] = {upk[2*ks][0], upk[2*ks][1],
                                      upk[2*ks+1][0], upk[2*ks+1][1]};
                    unsigned bh2[2] = {FB2(ml,ks,0,0), FB2(ml,ks,1,0)};
                    unsigned bl2[2] = {FB2(ml,ks,0,1), FB2(ml,ks,1,1)};
                    mma_bf16(acc2, a2, bh2);
                    mma_bf16(acc2, a2, bl2);
                }
                pacc[0] += acc2[0]; pacc[1] += acc2[1];
                pacc[2] += acc2[2]; pacc[3] += acc2[3];
            }
            // scores RMW: c0:(j=jbase+g, h=2tig) c1:(j, h+1) c2:(j+8, h) c3:(j+8, h+1)
            int i = i0 + ii;
            float* s0 = &g_scores[((b*HH + 2*tig)*NN + i)*NN + jbase];
            float* s1 = &g_scores[((b*HH + 2*tig + 1)*NN + i)*NN + jbase];
            s0[g]     += 0.1f * pacc[0];
            s1[g]     += 0.1f * pacc[1];
            s0[g + 8] += 0.1f * pacc[2];
            s1[g + 8] += 0.1f * pacc[3];
        }
    }
}

// ============================ softmax (unchanged) ===========================
__global__ void softmax_kernel()
{
    int warp = (blockIdx.x * blockDim.x + threadIdx.x) >> 5;
    int lane = threadIdx.x & 31;
    if (warp >= BB*HH*NN) return;
    float* row = &g_scores[(size_t)warp * NN];
    float4 v0 = *(float4*)&row[lane*8];
    float4 v1 = *(float4*)&row[lane*8 + 4];
    float mx = fmaxf(fmaxf(fmaxf(v0.x, v0.y), fmaxf(v0.z, v0.w)),
                     fmaxf(fmaxf(v1.x, v1.y), fmaxf(v1.z, v1.w)));
    #pragma unroll
    for (int o = 16; o > 0; o >>= 1)
        mx = fmaxf(mx, __shfl_xor_sync(0xffffffffu, mx, o));
    v0.x = __expf(v0.x - mx); v0.y = __expf(v0.y - mx);
    v0.z = __expf(v0.z - mx); v0.w = __expf(v0.w - mx);
    v1.x = __expf(v1.x - mx); v1.y = __expf(v1.y - mx);
    v1.z = __expf(v1.z - mx); v1.w = __expf(v1.w - mx);
    float sm = v0.x + v0.y + v0.z + v0.w + v1.x + v1.y + v1.z + v1.w;
    #pragma unroll
    for (int o = 16; o > 0; o >>= 1)
        sm += __shfl_xor_sync(0xffffffffu, sm, o);
    float inv = 1.f / sm;
    v0.x *= inv; v0.y *= inv; v0.z *= inv; v0.w *= inv;
    v1.x *= inv; v1.y *= inv; v1.z *= inv; v1.w *= inv;
    *(float4*)&row[lane*8]     = v0;
    *(float4*)&row[lane*8 + 4] = v1;
}

// ============================ attnv (unchanged) =============================
__global__ __launch_bounds__(256) void attnv_kernel()
{
    __shared__ float As[64*68];
    __shared__ float Vs[64*68];
    int t  = threadIdx.x;
    int tx = t & 15, ty = t >> 4;
    int i0 = blockIdx.x * 64;
    int bh = blockIdx.y; int b = bh >> 3, h = bh & 7;
    float acc[4][4] = {};

    for (int jc = 0; jc < NN; jc += 64) {
        #pragma unroll
        for (int u = 0; u < 4; u++) {
            int idx = t + u*256;
            int r = idx >> 4, c4 = (idx & 15) * 4;
            float4 a4 = *(const float4*)&g_scores[((b*HH + h)*NN + i0 + r)*NN + jc + c4];
            As[(c4+0)*68 + r] = a4.x; As[(c4+1)*68 + r] = a4.y;
            As[(c4+2)*68 + r] = a4.z; As[(c4+3)*68 + r] = a4.w;
            float4 v4 = *(const float4*)&g_vh[(b*NN + jc + r)*HIDD + h*64 + c4];
            *(float4*)&Vs[r*68 + c4] = v4;
        }
        __syncthreads();
        #pragma unroll 8
        for (int j = 0; j < 64; j++) {
            float4 a4 = *(const float4*)&As[j*68 + ty*4];
            float4 b4 = *(const float4*)&Vs[j*68 + tx*4];
            float av[4] = {a4.x, a4.y, a4.z, a4.w};
            float bv[4] = {b4.x, b4.y, b4.z, b4.w};
            #pragma unroll
            for (int i = 0; i < 4; i++)
                #pragma unroll
                for (int j2 = 0; j2 < 4; j2++)
                    acc[i][j2] += av[i] * bv[j2];
        }
        __syncthreads();
    }
    #pragma unroll
    for (int i = 0; i < 4; i++) {
        float4 o = {acc[i][0], acc[i][1], acc[i][2], acc[i][3]};
        *(float4*)&g_x[(b*NN + i0 + ty*4 + i)*HIDD + h*64 + tx*4] = o;
    }
}

// ===========================================================================
extern "C" void kernel_launch(void* const* d_in, const int* in_sizes, int n_in,
                              void* d_out, int out_size)
{
    const float* q     = (const float*)d_in[0];
    const float* k     = (const float*)d_in[1];
    const float* v     = (const float*)d_in[2];
    const float* tbias = (const float*)d_in[3];
    const float* fs    = (const float*)d_in[4];
    const float* fo    = (const float*)d_in[5];
    const float* Wq    = (const float*)d_in[6];
    const float* bq    = (const float*)d_in[7];
    const float* Wk    = (const float*)d_in[8];
    const float* bk    = (const float*)d_in[9];
    const float* Wv    = (const float*)d_in[10];
    const float* bv    = (const float*)d_in[11];
    const float* Wo    = (const float*)d_in[12];
    const float* bo    = (const float*)d_in[13];
    const float* fsW1  = (const float*)d_in[14];
    const float* fsb1  = (const float*)d_in[15];
    const float* fsW2  = (const float*)d_in[16];
    const float* fsb2  = (const float*)d_in[17];
    const float* foW1  = (const float*)d_in[18];
    const float* fob1  = (const float*)d_in[19];
    const float* foW2  = (const float*)d_in[20];
    const float* fob2  = (const float*)d_in[21];
    float* out = (float*)d_out;

    float* qh; cudaGetSymbolAddress((void**)&qh, g_qh);
    float* kh; cudaGetSymbolAddress((void**)&kh, g_kh);
    float* vh; cudaGetSymbolAddress((void**)&vh, g_vh);
    float* x;  cudaGetSymbolAddress((void**)&x,  g_x);
    __nv_bfloat16* Ahi;  cudaGetSymbolAddress((void**)&Ahi,  g_Ahi);
    __nv_bfloat16* Alo;  cudaGetSymbolAddress((void**)&Alo,  g_Alo);
    __nv_bfloat16* WhiT; cudaGetSymbolAddress((void**)&WhiT, g_WhiT);
    __nv_bfloat16* WloT; cudaGetSymbolAddress((void**)&WloT, g_WloT);

    cudaFuncSetAttribute(gemm_hmma_kernel,
                         cudaFuncAttributeMaxDynamicSharedMemorySize, SMEM_HM);
    cudaFuncSetAttribute(pair_mma_kernel,
                         cudaFuncAttributeMaxDynamicSharedMemorySize, PAIR_SMEMF*4);

    const int n4 = BN*HIDD/4;
    dim3 gw(16, 16);
    dim3 ghm(4, 32);

    // Q projection (scale folds 1/sqrt(dk))
    prep_a_kernel<<<(n4 + 255)/256, 256>>>(q, Ahi, Alo, n4);
    prep_w_kernel<<<gw, 256>>>(Wq, WhiT, WloT);
    gemm_hmma_kernel<<<ghm, 256, SMEM_HM>>>(Ahi, Alo, WhiT, WloT, bq, qh, 0.125f);
    // K projection
    prep_a_kernel<<<(n4 + 255)/256, 256>>>(k, Ahi, Alo, n4);
    prep_w_kernel<<<gw, 256>>>(Wk, WhiT, WloT);
    gemm_hmma_kernel<<<ghm, 256, SMEM_HM>>>(Ahi, Alo, WhiT, WloT, bk, kh, 1.0f);
    // V projection
    prep_a_kernel<<<(n4 + 255)/256, 256>>>(v, Ahi, Alo, n4);
    prep_w_kernel<<<gw, 256>>>(Wv, WhiT, WloT);
    gemm_hmma_kernel<<<ghm, 256, SMEM_HM>>>(Ahi, Alo, WhiT, WloT, bv, vh, 1.0f);

    hfeat_kernel<<<(BN*MLPH + 255)/256, 256>>>(fs, fo, fsW1, fsb1, foW1, fob1);

    scores_kernel<<<dim3(4, 4, BB*HH), 256>>>(tbias);

    pair_mma_kernel<<<dim3(16, BB), 256, PAIR_SMEMF*4>>>(fs, fo, fsW1, fsW2, fsb2,
                                                         foW1, foW2, fob2);

    softmax_kernel<<<(BB*HH*NN*32 + 255)/256, 256>>>();

    attnv_kernel<<<dim3(4, BB*HH), 256>>>();

    // Output projection
    prep_a_kernel<<<(n4 + 255)/256, 256>>>(x, Ahi, Alo, n4);
    prep_w_kernel<<<gw, 256>>>(Wo, WhiT, WloT);
    gemm_hmma_kernel<<<ghm, 256, SMEM_HM>>>(Ahi, Alo, WhiT, WloT, bo, out, 1.0f);
}